// round 12
// baseline (speedup 1.0000x reference)
#include <cuda_runtime.h>
#include <cuda_bf16.h>
#include <mma.h>
#include <stdint.h>

using namespace nvcuda;

// Problem constants
#define BB 4
#define SS 2048
#define EE 1024
#define HH 16
#define DD 64
#define MTOT (BB*SS)   // 8192
#define SCALING 0.125f

// Scratch (allocation-free rule: __device__ globals)
__device__ float g_q[BB*HH*SS*DD];    // [B,H,S,D]
__device__ float g_k[BB*HH*SS*DD];
__device__ float g_v[BB*HH*SS*DD];
__device__ float g_att[BB*SS*EE];     // [B,S,E]

__device__ __forceinline__ float to_tf32(float x) {
    uint32_t u; asm("cvt.rna.tf32.f32 %0, %1;" : "=r"(u) : "f"(x));
    return __uint_as_float(u);
}

__device__ __forceinline__ void mma_tf32(float* c,
    uint32_t a0, uint32_t a1, uint32_t a2, uint32_t a3,
    uint32_t b0, uint32_t b1)
{
    asm volatile("mma.sync.aligned.m16n8k8.row.col.f32.tf32.tf32.f32 "
        "{%0,%1,%2,%3},{%4,%5,%6,%7},{%8,%9},{%0,%1,%2,%3};\n"
        : "+f"(c[0]), "+f"(c[1]), "+f"(c[2]), "+f"(c[3])
        : "r"(a0), "r"(a1), "r"(a2), "r"(a3), "r"(b0), "r"(b1));
}

// within-8 column permutation: puts cols c and c+4 adjacent (float2 frag loads)
__device__ __forceinline__ int perm8(int c) { return 2 * (c & 3) + ((c >> 2) & 1); }

// ---------------------------------------------------------------------------
// Projection GEMM: C[M,N] = A[M,K] @ W[N,K]^T + bias. bf16 split-3 (hi/lo).
// DOUBLE-BUFFERED: MMA(stage s) -> fill(stage s^1) -> one sync per chunk.
// 128x128 tile, BK=32, 256 thr. blockIdx.z selects among 3 (A,W,b,out) sets.
// ---------------------------------------------------------------------------
#define PK 32
#define PLB 40                      // bf16 row pitch
#define PLDC 132
#define STAGE_BF (4*128*PLB)        // bf16 elems per stage (Ahi,Alo,Whi,Wlo)
#define PROJ_SMEM (2*STAGE_BF*2)    // 81920 B; Cs (67584 B) aliases

__global__ __launch_bounds__(256, 2)
void proj_all(const float* __restrict__ A0, const float* __restrict__ A1, const float* __restrict__ A2,
              const float* __restrict__ W0, const float* __restrict__ W1, const float* __restrict__ W2,
              const float* __restrict__ B0, const float* __restrict__ B1, const float* __restrict__ B2,
              float* __restrict__ O0, float* __restrict__ O1, float* __restrict__ O2,
              int mode)
{
    extern __shared__ char smraw[];
    float* Cs = (float*)smraw;   // epilogue staging aliases the stage tiles

    const int z = blockIdx.z;
    const float* A = (z == 0) ? A0 : (z == 1) ? A1 : A2;
    const float* W = (z == 0) ? W0 : (z == 1) ? W1 : W2;
    const float* bias = (z == 0) ? B0 : (z == 1) ? B1 : B2;
    float* out = (z == 0) ? O0 : (z == 1) ? O1 : O2;

    const int m0 = blockIdx.y * 128;
    const int n0 = blockIdx.x * 128;
    const int tid = threadIdx.x;
    const int wid = tid >> 5;
    const int wm = wid >> 2;   // 0..1
    const int wn = wid & 3;    // 0..3

    wmma::fragment<wmma::accumulator, 16, 16, 16, float> acc[4][2];
#pragma unroll
    for (int i = 0; i < 4; i++)
#pragma unroll
        for (int j = 0; j < 2; j++) wmma::fill_fragment(acc[i][j], 0.0f);

    const int r = tid >> 3;          // 0..31
    const int c4 = (tid & 7) * 4;    // 0..28

    // fill lambda: LDG + packed bf16x2 hi/lo split + STS to stage st
    auto fill = [&](int st, int k0) {
        __nv_bfloat16* Ahi = (__nv_bfloat16*)smraw + st * STAGE_BF;
        __nv_bfloat16* Alo = Ahi + 128 * PLB;
        __nv_bfloat16* Whi = Alo + 128 * PLB;
        __nv_bfloat16* Wlo = Whi + 128 * PLB;
#pragma unroll
        for (int p = 0; p < 4; p++) {
            int row = r + p * 32;
            float4 av = *(const float4*)&A[(size_t)(m0 + row) * EE + k0 + c4];
            float4 wv = *(const float4*)&W[(size_t)(n0 + row) * EE + k0 + c4];
            int o = row * PLB + c4;
            __nv_bfloat162 h01 = __float22bfloat162_rn(make_float2(av.x, av.y));
            __nv_bfloat162 h23 = __float22bfloat162_rn(make_float2(av.z, av.w));
            float2 f01 = __bfloat1622float2(h01);
            float2 f23 = __bfloat1622float2(h23);
            __nv_bfloat162 l01 = __float22bfloat162_rn(make_float2(av.x - f01.x, av.y - f01.y));
            __nv_bfloat162 l23 = __float22bfloat162_rn(make_float2(av.z - f23.x, av.w - f23.y));
            *(__nv_bfloat162*)&Ahi[o + 0] = h01;
            *(__nv_bfloat162*)&Ahi[o + 2] = h23;
            *(__nv_bfloat162*)&Alo[o + 0] = l01;
            *(__nv_bfloat162*)&Alo[o + 2] = l23;
            __nv_bfloat162 g01 = __float22bfloat162_rn(make_float2(wv.x, wv.y));
            __nv_bfloat162 g23 = __float22bfloat162_rn(make_float2(wv.z, wv.w));
            float2 e01 = __bfloat1622float2(g01);
            float2 e23 = __bfloat1622float2(g23);
            __nv_bfloat162 m01 = __float22bfloat162_rn(make_float2(wv.x - e01.x, wv.y - e01.y));
            __nv_bfloat162 m23 = __float22bfloat162_rn(make_float2(wv.z - e23.x, wv.w - e23.y));
            *(__nv_bfloat162*)&Whi[o + 0] = g01;
            *(__nv_bfloat162*)&Whi[o + 2] = g23;
            *(__nv_bfloat162*)&Wlo[o + 0] = m01;
            *(__nv_bfloat162*)&Wlo[o + 2] = m23;
        }
    };

    fill(0, 0);
    __syncthreads();

    for (int it = 0; it < EE / PK; it++) {
        const int s = it & 1;
        __nv_bfloat16* Ahi = (__nv_bfloat16*)smraw + s * STAGE_BF;
        __nv_bfloat16* Alo = Ahi + 128 * PLB;
        __nv_bfloat16* Whi = Alo + 128 * PLB;
        __nv_bfloat16* Wlo = Whi + 128 * PLB;

#pragma unroll
        for (int kk = 0; kk < PK; kk += 16) {
            wmma::fragment<wmma::matrix_b, 16, 16, 16, __nv_bfloat16, wmma::col_major> bhi[2], blo[2];
#pragma unroll
            for (int j = 0; j < 2; j++) {
                wmma::load_matrix_sync(bhi[j], &Whi[(wn * 32 + j * 16) * PLB + kk], PLB);
                wmma::load_matrix_sync(blo[j], &Wlo[(wn * 32 + j * 16) * PLB + kk], PLB);
            }
#pragma unroll
            for (int i = 0; i < 4; i++) {
                wmma::fragment<wmma::matrix_a, 16, 16, 16, __nv_bfloat16, wmma::row_major> ahi, alo;
                wmma::load_matrix_sync(ahi, &Ahi[(wm * 64 + i * 16) * PLB + kk], PLB);
                wmma::load_matrix_sync(alo, &Alo[(wm * 64 + i * 16) * PLB + kk], PLB);
#pragma unroll
                for (int j = 0; j < 2; j++) {
                    wmma::mma_sync(acc[i][j], ahi, bhi[j], acc[i][j]);
                    wmma::mma_sync(acc[i][j], ahi, blo[j], acc[i][j]);
                    wmma::mma_sync(acc[i][j], alo, bhi[j], acc[i][j]);
                }
            }
        }

        const int k0n = (it + 1) * PK;
        if (k0n < EE) fill(s ^ 1, k0n);
        __syncthreads();
    }

#pragma unroll
    for (int i = 0; i < 4; i++)
#pragma unroll
        for (int j = 0; j < 2; j++)
            wmma::store_matrix_sync(&Cs[(wm * 64 + i * 16) * PLDC + wn * 32 + j * 16],
                                    acc[i][j], PLDC, wmma::mem_row_major);
    __syncthreads();

    {
        int cc = (tid & 31) * 4;
        int n = n0 + cc;
        float4 bv = *(const float4*)&bias[n];
        int h = n >> 6, d0 = n & 63;
        for (int rp = 0; rp < 16; rp++) {
            int row = (tid >> 5) + rp * 8;
            int m = m0 + row;
            float4 v = *(float4*)&Cs[row * PLDC + cc];
            v.x += bv.x; v.y += bv.y; v.z += bv.z; v.w += bv.w;
            if (mode == 0) {
                int b = m >> 11, s2 = m & 2047;
                *(float4*)&out[(((size_t)(b * HH + h)) * SS + s2) * DD + d0] = v;
            } else {
                *(float4*)&out[(size_t)m * EE + n] = v;
            }
        }
    }
}

// ---------------------------------------------------------------------------
// Flash attention v6 (measured-good, unchanged from R11): 256 thr, 8 warps x
// 16 q-rows, register P -> PV, KT=128 fills, LDK=72 / LDKV=136 conflict-free.
// ---------------------------------------------------------------------------
#define LDK 72
#define LDKV 136
#define ATTN_SMEM ((128*LDK + 128*LDK + 64*LDKV)*4)  // 108544 B

__global__ __launch_bounds__(256, 2)
void attn_kernel(const float* __restrict__ Q, const float* __restrict__ K,
                 const float* __restrict__ V, float* __restrict__ out)
{
    extern __shared__ float sm[];
    float* Qs = sm;                   // [128][LDK]  tf32, cols permuted, pre-scaled
    float* Ks = Qs + 128 * LDK;       // [128][LDK]  tf32, d-cols permuted (128 kt rows)
    float* Vt = Ks + 128 * LDK;       // [64][LDKV]  V transposed [d][kt 0..127]

    const int tid = threadIdx.x;
    const int w = tid >> 5;           // 0..7
    const int l = tid & 31;
    const int qa = l >> 2;            // 0..7
    const int cq = l & 3;             // 0..3
    const int q0 = blockIdx.x * 128;
    const int bh = blockIdx.y;        // b*H + h
    const size_t base = (size_t)bh * SS * DD;

    // Load Q tile: scale, tf32, permute cols. 2 threads per row.
    {
        int row = tid >> 1;
        int cb = (tid & 1) * 32;
        const float* src = &Q[base + (size_t)(q0 + row) * DD + cb];
        float* dst = &Qs[row * LDK + cb];
#pragma unroll
        for (int b = 0; b < 4; b++) {
            float4 x = *(const float4*)&src[b * 8];
            float4 y = *(const float4*)&src[b * 8 + 4];
            float4 v1 = make_float4(to_tf32(x.x * SCALING), to_tf32(y.x * SCALING),
                                    to_tf32(x.y * SCALING), to_tf32(y.y * SCALING));
            float4 v2 = make_float4(to_tf32(x.z * SCALING), to_tf32(y.z * SCALING),
                                    to_tf32(x.w * SCALING), to_tf32(y.w * SCALING));
            *(float4*)&dst[b * 8] = v1;
            *(float4*)&dst[b * 8 + 4] = v2;
        }
    }

    float m_[2] = {-1e30f, -1e30f};
    float l_[2] = {0.f, 0.f};
    float o_[8][4];
#pragma unroll
    for (int dg = 0; dg < 8; dg++)
#pragma unroll
        for (int e = 0; e < 4; e++) o_[dg][e] = 0.f;

    for (int kt = 0; kt < SS / 128; kt++) {     // 16 fills
        __syncthreads();
        const int t0 = kt * 128;
        // ---- K fill: row = kt-in-tile, interleaved-pair float4 stores
        {
            int row = tid >> 1;               // 0..127
            int half = (tid & 1) * 32;
            const float* ksrc = &K[base + (size_t)(t0 + row) * DD + half];
            float* kdst = &Ks[row * LDK + half];
#pragma unroll
            for (int b = 0; b < 4; b++) {
                float4 x = *(const float4*)&ksrc[b * 8];
                float4 y = *(const float4*)&ksrc[b * 8 + 4];
                float4 v1 = make_float4(to_tf32(x.x), to_tf32(y.x), to_tf32(x.y), to_tf32(y.y));
                float4 v2 = make_float4(to_tf32(x.z), to_tf32(y.z), to_tf32(x.w), to_tf32(y.w));
                *(float4*)&kdst[b * 8] = v1;
                *(float4*)&kdst[b * 8 + 4] = v2;
            }
        }
        // ---- V fill: one d-col per thread-slot, float4 runs along kt
        {
            int d = l + 32 * (w & 1);         // 0..63
            int ktq = (w >> 1) * 32;          // 0,32,64,96
            const float* vsrc = &V[base + (size_t)(t0 + ktq) * DD + d];
            float* vdst = &Vt[d * LDKV + ktq];
#pragma unroll
            for (int g = 0; g < 8; g++) {
                float a0 = vsrc[(g * 4 + 0) * DD];
                float a1 = vsrc[(g * 4 + 1) * DD];
                float a2 = vsrc[(g * 4 + 2) * DD];
                float a3 = vsrc[(g * 4 + 3) * DD];
                *(float4*)&vdst[g * 4] =
                    make_float4(to_tf32(a0), to_tf32(a1), to_tf32(a2), to_tf32(a3));
            }
        }
        __syncthreads();

#pragma unroll
        for (int ch = 0; ch < 2; ch++) {
            const float* KsC = Ks + ch * 64 * LDK;
            const float* VtC = Vt + ch * 64;

            // ---- scores: 16 q-rows x 64 kt per warp
            float s[8][4];
#pragma unroll
            for (int ng = 0; ng < 8; ng++) {
                s[ng][0] = 0.f; s[ng][1] = 0.f; s[ng][2] = 0.f; s[ng][3] = 0.f;
            }
            const int r0 = w * 16 + qa;
#pragma unroll
            for (int kk = 0; kk < 8; kk++) {
                float2 aA = *(float2*)&Qs[(r0)     * LDK + kk * 8 + 2 * cq];
                float2 aB = *(float2*)&Qs[(r0 + 8) * LDK + kk * 8 + 2 * cq];
                uint32_t a0 = __float_as_uint(aA.x), a1 = __float_as_uint(aB.x);
                uint32_t a2 = __float_as_uint(aA.y), a3 = __float_as_uint(aB.y);
#pragma unroll
                for (int ng = 0; ng < 8; ng++) {
                    float2 bv = *(float2*)&KsC[(ng * 8 + qa) * LDK + kk * 8 + 2 * cq];
                    mma_tf32(s[ng], a0, a1, a2, a3,
                             __float_as_uint(bv.x), __float_as_uint(bv.y));
                }
            }

            // ---- online softmax in registers (rows r0, r0+8)
            float mxa = -1e30f, mxb = -1e30f;
#pragma unroll
            for (int ng = 0; ng < 8; ng++) {
                mxa = fmaxf(mxa, fmaxf(s[ng][0], s[ng][1]));
                mxb = fmaxf(mxb, fmaxf(s[ng][2], s[ng][3]));
            }
            mxa = fmaxf(mxa, __shfl_xor_sync(0xffffffffu, mxa, 1));
            mxa = fmaxf(mxa, __shfl_xor_sync(0xffffffffu, mxa, 2));
            mxb = fmaxf(mxb, __shfl_xor_sync(0xffffffffu, mxb, 1));
            mxb = fmaxf(mxb, __shfl_xor_sync(0xffffffffu, mxb, 2));
            float mna = fmaxf(m_[0], mxa), mnb = fmaxf(m_[1], mxb);
            float suma = 0.f, sumb = 0.f;
#pragma unroll
            for (int ng = 0; ng < 8; ng++) {
                float p0 = to_tf32(__expf(s[ng][0] - mna));
                float p1 = to_tf32(__expf(s[ng][1] - mna));
                float p2 = to_tf32(__expf(s[ng][2] - mnb));
                float p3 = to_tf32(__expf(s[ng][3] - mnb));
                suma += p0 + p1;  sumb += p2 + p3;
                s[ng][0] = p0; s[ng][1] = p1; s[ng][2] = p2; s[ng][3] = p3;
            }
            suma += __shfl_xor_sync(0xffffffffu, suma, 1);
            suma += __shfl_xor_sync(0xffffffffu, suma, 2);
            sumb += __shfl_xor_sync(0xffffffffu, sumb, 1);
            sumb += __shfl_xor_sync(0xffffffffu, sumb, 2);
            float ala = __expf(m_[0] - mna), alb = __expf(m_[1] - mnb);
            m_[0] = mna; m_[1] = mnb;
            l_[0] = l_[0] * ala + suma;
            l_[1] = l_[1] * alb + sumb;
#pragma unroll
            for (int dg = 0; dg < 8; dg++) {
                o_[dg][0] *= ala; o_[dg][1] *= ala;
                o_[dg][2] *= alb; o_[dg][3] *= alb;
            }

            // ---- PV: O(16x64) += P(16x64) @ V(64x64); P straight from s regs
            // A slots: a0 = c0 (kt 2cq), a1 = c2, a2 = c1 (kt 2cq+1), a3 = c3
#pragma unroll
            for (int ng = 0; ng < 8; ng++) {
                uint32_t p0 = __float_as_uint(s[ng][0]), p1 = __float_as_uint(s[ng][1]);
                uint32_t p2 = __float_as_uint(s[ng][2]), p3 = __float_as_uint(s[ng][3]);
#pragma unroll
                for (int dg = 0; dg < 8; dg++) {
                    float2 bv = *(float2*)&VtC[(dg * 8 + qa) * LDKV + ng * 8 + 2 * cq];
                    mma_tf32(o_[dg], p0, p2, p1, p3,
                             __float_as_uint(bv.x), __float_as_uint(bv.y));
                }
            }
        }
    }

    // Final: O /= l, write [B,S,E] at column h*64
    {
        int b = bh >> 4, h = bh & 15;
        float inva = 1.0f / l_[0], invb = 1.0f / l_[1];
        int rowa = q0 + w * 16 + qa;
        int rowb = rowa + 8;
#pragma unroll
        for (int dg = 0; dg < 8; dg++) {
            int col = h * 64 + dg * 8 + 2 * cq;
            float2 va = make_float2(o_[dg][0] * inva, o_[dg][1] * inva);
            float2 vb = make_float2(o_[dg][2] * invb, o_[dg][3] * invb);
            *(float2*)&out[((size_t)b * SS + rowa) * EE + col] = va;
            *(float2*)&out[((size_t)b * SS + rowb) * EE + col] = vb;
        }
    }
}

// ---------------------------------------------------------------------------
extern "C" void kernel_launch(void* const* d_in, const int* in_sizes, int n_in,
                              void* d_out, int out_size)
{
    const float* query = (const float*)d_in[0];
    const float* key   = (const float*)d_in[1];
    const float* value = (const float*)d_in[2];
    const float* q_w   = (const float*)d_in[3];
    const float* q_b   = (const float*)d_in[4];
    const float* k_w   = (const float*)d_in[5];
    const float* k_b   = (const float*)d_in[6];
    const float* v_w   = (const float*)d_in[7];
    const float* v_b   = (const float*)d_in[8];
    const float* out_w = (const float*)d_in[9];
    const float* out_b = (const float*)d_in[10];
    float* out = (float*)d_out;

    float *gq, *gk, *gv, *gatt;
    cudaGetSymbolAddress((void**)&gq, g_q);
    cudaGetSymbolAddress((void**)&gk, g_k);
    cudaGetSymbolAddress((void**)&gv, g_v);
    cudaGetSymbolAddress((void**)&gatt, g_att);

    cudaFuncSetAttribute(proj_all, cudaFuncAttributeMaxDynamicSharedMemorySize, PROJ_SMEM);
    cudaFuncSetAttribute(attn_kernel, cudaFuncAttributeMaxDynamicSharedMemorySize, ATTN_SMEM);

    // Q/K/V projections in ONE launch (grid.z selects the set)
    dim3 pgrid3(EE / 128, MTOT / 128, 3);   // (8, 64, 3)
    proj_all<<<pgrid3, 256, PROJ_SMEM>>>(query, key, value,
                                         q_w, k_w, v_w,
                                         q_b, k_b, v_b,
                                         gq, gk, gv, 0);

    // Attention
    dim3 agrid(SS / 128, BB * HH);          // (16, 64)
    attn_kernel<<<agrid, 256, ATTN_SMEM>>>(gq, gk, gv, gatt);

    // Output projection
    dim3 pgrid1(EE / 128, MTOT / 128, 1);
    proj_all<<<pgrid1, 256, PROJ_SMEM>>>(gatt, gatt, gatt,
                                         out_w, out_w, out_w,
                                         out_b, out_b, out_b,
                                         out, out, out, 1);
}